// round 11
// baseline (speedup 1.0000x reference)
#include <cuda_runtime.h>
#include <cstdint>

// ============================================================================
// QuantumNeuralLayer: out = x @ W.T + (b + 0.1*q); q batch-independent.
// 262144x256x64 fp32 GEMM via mma.sync fp16.
// R11: NO cp.async, NO SMEM staging for A, NO main-loop barriers. A fragments
// load straight GMEM->registers via LDG.64 (sector-perfect; L1 reuses the
// second half of each 128B line on the next k-stage), register double-buffer
// one stage ahead. Evidence R6-R10: the cp.async ring pinned at ~4.6TB/s
// regardless of warps/CTAs/dtype — the staged-burst handshake was the pacer.
// W fragments (true reuse) stay in SMEM (32KB); 2 CTAs/SM, 16 warps/SM.
// ============================================================================

#define INV_SQRT2 0.70710678118654752440f

static constexpr int B_TOTAL = 262144;
static constexpr int KDIM    = 256;
static constexpr int ODIM    = 64;
static constexpr int TILE_M  = 256;                 // 8 warps x 32 rows
static constexpr int NTILES  = B_TOTAL / TILE_M;    // 1024
static constexpr int NTHREADS = 256;
static constexpr int SPT     = 16;                  // k16 stages per tile

__device__ float g_bias[64];   // b + 0.1*quantum; all CTAs write same values

// ---------------------------------------------------------------------------
__device__ __forceinline__ uint32_t f2h2(float lo, float hi) {
    uint32_t r;
    asm("cvt.rn.f16x2.f32 %0, %1, %2;" : "=r"(r) : "f"(hi), "f"(lo));
    return r;
}
__device__ __forceinline__ uint32_t f2h2v(float2 v) { return f2h2(v.x, v.y); }

__device__ __forceinline__ void mma_f16(float c[4], uint32_t a0, uint32_t a1,
                                        uint32_t a2, uint32_t a3,
                                        uint32_t b0, uint32_t b1) {
    asm volatile(
        "mma.sync.aligned.m16n8k16.row.col.f32.f16.f16.f32 "
        "{%0,%1,%2,%3}, {%4,%5,%6,%7}, {%8,%9}, {%0,%1,%2,%3};"
        : "+f"(c[0]), "+f"(c[1]), "+f"(c[2]), "+f"(c[3])
        : "r"(a0), "r"(a1), "r"(a2), "r"(a3), "r"(b0), "r"(b1));
}

// ---------------------------------------------------------------------------
__global__ void __launch_bounds__(NTHREADS, 2)
qnl_kernel(const float* __restrict__ x, const float* __restrict__ W,
           const float* __restrict__ bvec, const float* __restrict__ phase,
           const float* __restrict__ ent, float* __restrict__ out) {
    __shared__ uint2 sWf[4096];        // W fragments [s(16)][nt(8)][lane(32)]
    __shared__ float sha[64], shc[64]; // bias prep scratch

    const int tid  = threadIdx.x;
    const int wid  = tid >> 5;
    const int lane = tid & 31;
    const int grid = gridDim.x;
    const int bid  = blockIdx.x;

    // Warp owns rows [wid*32, wid*32+32); per-thread base row = +（lane>>2).
    const int wrow = wid * 32;
    const int arow = wrow + (lane >> 2);

    const int ntile_local = (NTILES - bid + grid - 1) / grid;
    const int H = SPT * ntile_local;

    // Per-thread GMEM pointer for stage jq (tile bid+(jq>>4)*grid, k16 (jq&15)).
    auto aptr = [&](int jq) -> const float* {
        const int tile = bid + (jq >> 4) * grid;
        const int kb = (jq & 15) * 16;
        return x + (size_t)(tile * TILE_M + arow) * KDIM + kb + 2 * (lane & 3);
    };

    // A-fragment raw loads: rows +{0,8,16,24}, col-pairs +{0,8}. 8 x LDG.64.
    float2 raw[8];
    auto lda = [&](const float* p) {
#pragma unroll
        for (int r = 0; r < 4; r++) {
            raw[r * 2 + 0] = *(const float2*)(p + (size_t)(r * 8) * KDIM);
            raw[r * 2 + 1] = *(const float2*)(p + (size_t)(r * 8) * KDIM + 8);
        }
    };

    lda(aptr(0));   // prefetch stage 0 while we do prep below

    // --- W fragments, fp16x2: uint2{b0,b1} per (s, nt, lane) ---
    for (int e = tid; e < 4096; e += NTHREADS) {
        int le = e & 31;
        int nt = (e >> 5) & 7;
        int s  = e >> 8;
        int n = nt * 8 + (le >> 2);
        int k = s * 16 + 2 * (le & 3);
        const float* wr = W + n * KDIM + k;
        uint2 wv;
        wv.x = f2h2(wr[0], wr[1]);
        wv.y = f2h2(wr[8], wr[9]);
        sWf[e] = wv;
    }

    // --- bias_eff = b + 0.1*quantum (batch-independent) ---
    {
        float a = 1.0f, c = 0.0f;
        for (int d = 0; d < 3; d++) {
            if (tid < 64) {
                float ph = phase[d * 64 + tid];
                sha[tid] = (a + c) * INV_SQRT2 * sinf(ph);
                shc[tid] = (a - c) * INV_SQRT2 * cosf(ph);
            }
            __syncthreads();
            if (tid < 64) {
                float sa = 0.0f, sc = 0.0f;
#pragma unroll
                for (int i = 0; i < 64; i++) {
                    float e = ent[i * 64 + tid];
                    sa += sha[i] * e;
                    sc += shc[i] * e;
                }
                a = sa; c = sc;
            }
            __syncthreads();
        }
        if (tid < 64) g_bias[tid] = bvec[tid] + 0.1f * (a * a + c * c);
    }
    __syncthreads();   // sWf visible; last barrier in the kernel

    float acc[2][8][4];
#pragma unroll
    for (int mb = 0; mb < 2; mb++)
#pragma unroll
        for (int nt = 0; nt < 8; nt++)
#pragma unroll
            for (int q = 0; q < 4; q++) acc[mb][nt][q] = 0.0f;

    for (int j = 0; j < H; j++) {
        // Convert this stage's raw A to fp16x2 (scoreboard-waits on the LDGs
        // issued one stage ago — the only pacing point in the loop).
        uint32_t cur[8];
#pragma unroll
        for (int i = 0; i < 8; i++) cur[i] = f2h2v(raw[i]);

        if (j + 1 < H) lda(aptr(j + 1));   // prefetch next stage into raw

        const int s = j & 15;
#pragma unroll
        for (int nt = 0; nt < 8; nt++) {
            uint2 wv = sWf[(s * 8 + nt) * 32 + lane];
            // rows arow/+8 (mb0): raw layout a0=cur0, a1=cur2, a2=cur1, a3=cur3
            mma_f16(acc[0][nt], cur[0], cur[2], cur[1], cur[3], wv.x, wv.y);
            // rows +16/+24 (mb1)
            mma_f16(acc[1][nt], cur[4], cur[6], cur[5], cur[7], wv.x, wv.y);
        }

        if ((j & 15) == 15) {
            // Tile complete: per-warp epilogue; bias via global (L1/L2 hit).
            const int tile = bid + (j >> 4) * grid;
            const int row0 = tile * TILE_M + arow;
            float* o0 = out + (size_t)row0 * ODIM + 2 * (lane & 3);
#pragma unroll
            for (int mb = 0; mb < 2; mb++) {
                float* om = o0 + (size_t)(mb * 16) * ODIM;
#pragma unroll
                for (int nt = 0; nt < 8; nt++) {
                    const int cb = nt * 8;
                    float bx = g_bias[cb + 2 * (lane & 3)];
                    float by = g_bias[cb + 2 * (lane & 3) + 1];
                    float2 v0 = {acc[mb][nt][0] + bx, acc[mb][nt][1] + by};
                    float2 v1 = {acc[mb][nt][2] + bx, acc[mb][nt][3] + by};
                    *(float2*)(om + cb)            = v0;
                    *(float2*)(om + cb + 8 * ODIM) = v1;
                    acc[mb][nt][0] = acc[mb][nt][1] = 0.0f;
                    acc[mb][nt][2] = acc[mb][nt][3] = 0.0f;
                }
            }
        }
    }
}

// ---------------------------------------------------------------------------
extern "C" void kernel_launch(void* const* d_in, const int* in_sizes, int n_in,
                              void* d_out, int out_size) {
    const float* x   = (const float*)d_in[0];
    const float* W   = (const float*)d_in[1];
    const float* b   = (const float*)d_in[2];
    const float* ps  = (const float*)d_in[3];
    const float* ent = (const float*)d_in[4];
    float* out = (float*)d_out;

    int sm = 148;
    cudaDeviceGetAttribute(&sm, cudaDevAttrMultiProcessorCount, 0);
    int grid = 2 * sm;                  // 2 CTAs per SM (33 KB SMEM each)
    if (grid > NTILES) grid = NTILES;

    qnl_kernel<<<grid, NTHREADS>>>(x, W, b, ps, ent, out);
}